// round 9
// baseline (speedup 1.0000x reference)
#include <cuda_runtime.h>
#include <cstdint>

// Inv1x1MM_SVD, C=16, 65536 positions.
// LANE-LOCAL layout: ONE position per lane. The 16x16 working matrix lives in
// 128 registers as column pairs: A[i][c] = row i, cols {2c, 2c+1} (f32x2).
// MGS is entirely lane-local: zero shuffles, zero syncs; dep chain per step is
// dot-tree + rcp only. U's 1/||b|| goes to packed rs[8]; V's is folded into w.

constexpr int NPOS = 8 * 8192;

#define FMA2(d, a, b, c) asm("fma.rn.f32x2 %0, %1, %2, %3;" : "=l"(d) : "l"(a), "l"(b), "l"(c))
#define MUL2(d, a, b)    asm("mul.rn.f32x2 %0, %1, %2;"     : "=l"(d) : "l"(a), "l"(b))
#define ADD2(d, a, b)    asm("add.rn.f32x2 %0, %1, %2;"     : "=l"(d) : "l"(a), "l"(b))
#define PACK2(d, lo, hi) asm("mov.b64 %0, {%1, %2};"        : "=l"(d) : "f"(lo), "f"(hi))
#define UNPACK2(lo, hi, d) asm("mov.b64 {%0, %1}, %2;" : "=f"(lo), "=f"(hi) : "l"(d))

__device__ __forceinline__ float frcp(float x) {
    float r;
    asm("rcp.approx.f32 %0, %1;" : "=f"(r) : "f"(x));
    return r;
}

// Lane-local MGS over 16 columns (packed pairs).
// SCALEW=false: write 1/||b_k|| into half k of T (T = rs sink).
// SCALEW=true : multiply half k of T by 1/||b_k|| (T = w, folded scaling).
template <bool SCALEW>
__device__ __forceinline__ void mgs_local(uint64_t (&A)[16][8], uint64_t (&T)[8]) {
    #pragma unroll
    for (int k = 0; k < 15; k++) {
        const int c0 = k >> 1;        // pair containing column k
        const int cu = (k + 1) >> 1;  // first pair updated

        // duplicate column k into packed registers (lane-local)
        uint64_t ak[16];
        #pragma unroll
        for (int i = 0; i < 16; i++) {
            float lo, hi;
            UNPACK2(lo, hi, A[i][c0]);
            const float x = (k & 1) ? hi : lo;
            PACK2(ak[i], x, x);
        }

        // dots p_j = <c_k, c_j> for all pairs >= c0 (4 accumulator trees)
        uint64_t pp[8];
        #pragma unroll
        for (int c = c0; c < 8; c++) {
            uint64_t s0, s1, s2, s3;
            MUL2(s0, ak[0],  A[0][c]);
            MUL2(s1, ak[1],  A[1][c]);
            MUL2(s2, ak[2],  A[2][c]);
            MUL2(s3, ak[3],  A[3][c]);
            FMA2(s0, ak[4],  A[4][c],  s0);
            FMA2(s1, ak[5],  A[5][c],  s1);
            FMA2(s2, ak[6],  A[6][c],  s2);
            FMA2(s3, ak[7],  A[7][c],  s3);
            FMA2(s0, ak[8],  A[8][c],  s0);
            FMA2(s1, ak[9],  A[9][c],  s1);
            FMA2(s2, ak[10], A[10][c], s2);
            FMA2(s3, ak[11], A[11][c], s3);
            FMA2(s0, ak[12], A[12][c], s0);
            FMA2(s1, ak[13], A[13][c], s1);
            FMA2(s2, ak[14], A[14][c], s2);
            FMA2(s3, ak[15], A[15][c], s3);
            ADD2(s0, s0, s1);
            ADD2(s2, s2, s3);
            ADD2(pp[c], s0, s2);
        }

        // fresh norm ||c_k||^2 = p_k
        float plo, phi;
        UNPACK2(plo, phi, pp[c0]);
        const float pk = fmaxf((k & 1) ? phi : plo, 1e-30f);
        const float ninv = -frcp(pk);      // projection scale path
        const float r = rsqrtf(pk);        // normalization path (parallel MUFU)
        {
            float tl, th;
            UNPACK2(tl, th, T[c0]);
            if (SCALEW) {
                if (k & 1) th *= r; else tl *= r;
            } else {
                if (k & 1) th = r; else tl = r;
            }
            PACK2(T[c0], tl, th);
        }
        uint64_t n2;
        PACK2(n2, ninv, ninv);

        // c_j -= (p_j / ||c_k||^2) c_k  for j > k
        #pragma unroll
        for (int c = cu; c < 8; c++) {
            uint64_t s;
            MUL2(s, pp[c], n2);
            if (!(k & 1) && c == cu) {     // pair contains j == k: mask lo half
                float sl, sh;
                UNPACK2(sl, sh, s);
                PACK2(s, 0.0f, sh);
            }
            #pragma unroll
            for (int i = 0; i < 16; i++) FMA2(A[i][c], s, ak[i], A[i][c]);
        }
    }
    // column 15 norm
    {
        uint64_t s0, s1;
        MUL2(s0, A[0][7], A[0][7]);
        MUL2(s1, A[1][7], A[1][7]);
        #pragma unroll
        for (int i = 2; i < 16; i += 2) {
            FMA2(s0, A[i][7],     A[i][7],     s0);
            FMA2(s1, A[i + 1][7], A[i + 1][7], s1);
        }
        ADD2(s0, s0, s1);
        float nlo, n15;
        UNPACK2(nlo, n15, s0);
        const float r = rsqrtf(fmaxf(n15, 1e-30f));
        float tl, th;
        UNPACK2(tl, th, T[7]);
        if (SCALEW) th *= r; else th = r;
        PACK2(T[7], tl, th);
    }
}

__device__ __forceinline__ void load_mat(uint64_t (&A)[16][8], const float4* f4, int base) {
    #pragma unroll
    for (int i = 0; i < 16; i++) {
        const float4 q0 = __ldg(&f4[base + 4 * i + 0]);
        const float4 q1 = __ldg(&f4[base + 4 * i + 1]);
        const float4 q2 = __ldg(&f4[base + 4 * i + 2]);
        const float4 q3 = __ldg(&f4[base + 4 * i + 3]);
        PACK2(A[i][0], q0.x, q0.y); PACK2(A[i][1], q0.z, q0.w);
        PACK2(A[i][2], q1.x, q1.y); PACK2(A[i][3], q1.z, q1.w);
        PACK2(A[i][4], q2.x, q2.y); PACK2(A[i][5], q2.z, q2.w);
        PACK2(A[i][6], q3.x, q3.y); PACK2(A[i][7], q3.z, q3.w);
    }
}

__global__ void __launch_bounds__(128)
inv1x1mm_svd_kernel(const float* __restrict__ data,
                    const float* __restrict__ paras,
                    float* __restrict__ out) {
    const int pos = blockIdx.x * 128 + threadIdx.x;
    const float4* f4 = (const float4*)paras + (size_t)pos * 132;

    uint64_t A[16][8];

    // ===== QR of U =====
    load_mat(A, f4, 4);
    uint64_t rs[8];
    mgs_local<false>(A, rs);

    // v_j = <data, b0_j>  (two 8-row chunks), then w = v .* rs .* exp(ls)
    const float4* d4 = (const float4*)data + (size_t)pos * 4;
    uint64_t w[8];
    {
        const float4 dv0 = __ldg(&d4[0]);
        const float4 dv1 = __ldg(&d4[1]);
        uint64_t dd[8];
        PACK2(dd[0], dv0.x, dv0.x); PACK2(dd[1], dv0.y, dv0.y);
        PACK2(dd[2], dv0.z, dv0.z); PACK2(dd[3], dv0.w, dv0.w);
        PACK2(dd[4], dv1.x, dv1.x); PACK2(dd[5], dv1.y, dv1.y);
        PACK2(dd[6], dv1.z, dv1.z); PACK2(dd[7], dv1.w, dv1.w);
        #pragma unroll
        for (int c = 0; c < 8; c++) {
            uint64_t s0, s1;
            MUL2(s0, dd[0], A[0][c]);
            MUL2(s1, dd[1], A[1][c]);
            FMA2(s0, dd[2], A[2][c], s0);
            FMA2(s1, dd[3], A[3][c], s1);
            FMA2(s0, dd[4], A[4][c], s0);
            FMA2(s1, dd[5], A[5][c], s1);
            FMA2(s0, dd[6], A[6][c], s0);
            FMA2(s1, dd[7], A[7][c], s1);
            ADD2(w[c], s0, s1);
        }
        const float4 dv2 = __ldg(&d4[2]);
        const float4 dv3 = __ldg(&d4[3]);
        PACK2(dd[0], dv2.x, dv2.x); PACK2(dd[1], dv2.y, dv2.y);
        PACK2(dd[2], dv2.z, dv2.z); PACK2(dd[3], dv2.w, dv2.w);
        PACK2(dd[4], dv3.x, dv3.x); PACK2(dd[5], dv3.y, dv3.y);
        PACK2(dd[6], dv3.z, dv3.z); PACK2(dd[7], dv3.w, dv3.w);
        #pragma unroll
        for (int c = 0; c < 8; c++) {
            uint64_t s0, s1;
            MUL2(s0, dd[0], A[8][c]);
            MUL2(s1, dd[1], A[9][c]);
            FMA2(s0, dd[2], A[10][c], s0);
            FMA2(s1, dd[3], A[11][c], s1);
            FMA2(s0, dd[4], A[12][c], s0);
            FMA2(s1, dd[5], A[13][c], s1);
            FMA2(s0, dd[6], A[14][c], s0);
            FMA2(s1, dd[7], A[15][c], s1);
            ADD2(s0, s0, s1);
            ADD2(w[c], w[c], s0);
            MUL2(w[c], w[c], rs[c]);     // fold 1/||b0_j||
        }
    }
    {
        const float4 l0 = __ldg(&f4[0]);
        const float4 l1 = __ldg(&f4[1]);
        const float4 l2 = __ldg(&f4[2]);
        const float4 l3 = __ldg(&f4[3]);
        uint64_t e;
        PACK2(e, __expf(l0.x), __expf(l0.y)); MUL2(w[0], w[0], e);
        PACK2(e, __expf(l0.z), __expf(l0.w)); MUL2(w[1], w[1], e);
        PACK2(e, __expf(l1.x), __expf(l1.y)); MUL2(w[2], w[2], e);
        PACK2(e, __expf(l1.z), __expf(l1.w)); MUL2(w[3], w[3], e);
        PACK2(e, __expf(l2.x), __expf(l2.y)); MUL2(w[4], w[4], e);
        PACK2(e, __expf(l2.z), __expf(l2.w)); MUL2(w[5], w[5], e);
        PACK2(e, __expf(l3.x), __expf(l3.y)); MUL2(w[6], w[6], e);
        PACK2(e, __expf(l3.z), __expf(l3.w)); MUL2(w[7], w[7], e);
    }

    // ===== QR of V ===== (folds 1/||b1_j|| into w as columns finish)
    load_mat(A, f4, 68);
    mgs_local<true>(A, w);

    // res_d = sum_j w_j * b1[d][j], d = 0..15 (all lane-local)
    float* op = out + (size_t)pos * 16;
    #pragma unroll
    for (int i = 0; i < 16; i += 4) {
        float o[4];
        #pragma unroll
        for (int ii = 0; ii < 4; ii++) {
            const int row = i + ii;
            uint64_t s0, s1;
            MUL2(s0, w[0], A[row][0]);
            MUL2(s1, w[1], A[row][1]);
            FMA2(s0, w[2], A[row][2], s0);
            FMA2(s1, w[3], A[row][3], s1);
            FMA2(s0, w[4], A[row][4], s0);
            FMA2(s1, w[5], A[row][5], s1);
            FMA2(s0, w[6], A[row][6], s0);
            FMA2(s1, w[7], A[row][7], s1);
            ADD2(s0, s0, s1);
            float lo, hi;
            UNPACK2(lo, hi, s0);
            o[ii] = lo + hi;
        }
        *(float4*)(op + i) = make_float4(o[0], o[1], o[2], o[3]);
    }
}

extern "C" void kernel_launch(void* const* d_in, const int* in_sizes, int n_in,
                              void* d_out, int out_size) {
    const float* data  = (const float*)d_in[0];
    const float* paras = (const float*)d_in[1];
    if (n_in >= 2 && in_sizes[0] > in_sizes[1]) {  // defensive ordering by size
        data  = (const float*)d_in[1];
        paras = (const float*)d_in[0];
    }
    inv1x1mm_svd_kernel<<<NPOS / 128, 128>>>(data, paras, (float*)d_out);
}

// round 10
// speedup vs baseline: 1.4028x; 1.4028x over previous
#include <cuda_runtime.h>
#include <cstdint>

// Inv1x1MM_SVD, C=16, 65536 positions.
// ROW-SLAB layout, 2 lanes per position (R6 base): lane (pos, half) holds rows
// half*8..half*8+7 of the 16x16 working matrix, packed f32x2 column pairs.
// Register diet vs R6: rs0 -> shared memory (stride-17), rs1 folded into w
// on the fly (SCALEW), exp(ls) computed into one reused register. No prefetch.

constexpr int NPOS = 8 * 8192;

#define FMA2(d, a, b, c) asm("fma.rn.f32x2 %0, %1, %2, %3;" : "=l"(d) : "l"(a), "l"(b), "l"(c))
#define MUL2(d, a, b)    asm("mul.rn.f32x2 %0, %1, %2;"     : "=l"(d) : "l"(a), "l"(b), "l"(b))
#define ADD2(d, a, b)    asm("add.rn.f32x2 %0, %1, %2;"     : "=l"(d) : "l"(a), "l"(b))
#define PACK2(d, lo, hi) asm("mov.b64 %0, {%1, %2};"        : "=l"(d) : "f"(lo), "f"(hi))
#define UNPACK2(lo, hi, d) asm("mov.b64 {%0, %1}, %2;" : "=f"(lo), "=f"(hi) : "l"(d))

// fix MUL2 (three-operand)
#undef MUL2
#define MUL2(d, a, b)    asm("mul.rn.f32x2 %0, %1, %2;"     : "=l"(d) : "l"(a), "l"(b))

__device__ __forceinline__ uint64_t shx1(uint64_t v) {
    uint32_t lo, hi;
    asm("mov.b64 {%0, %1}, %2;" : "=r"(lo), "=r"(hi) : "l"(v));
    lo = __shfl_xor_sync(0xffffffffu, lo, 1);
    hi = __shfl_xor_sync(0xffffffffu, hi, 1);
    uint64_t r;
    asm("mov.b64 %0, {%1, %2};" : "=l"(r) : "r"(lo), "r"(hi));
    return r;
}
__device__ __forceinline__ float frcp(float x) {
    float r;
    asm("rcp.approx.f32 %0, %1;" : "=f"(r) : "f"(x));
    return r;
}

// MGS, rows split across a lane pair.
// SCALEW=false: writer lane stores 1/||b_k|| to rs_sm[k].
// SCALEW=true : fold 1/||b_k|| into w element k as columns finish.
template <bool SCALEW>
__device__ __forceinline__ void mgs2(uint64_t (&A)[8][8], uint64_t* w,
                                     float* rs_sm, bool writer) {
    #pragma unroll
    for (int k = 0; k < 15; k++) {
        const int c0 = k >> 1;
        const int cu = (k + 1) >> 1;

        uint64_t ak[8];
        #pragma unroll
        for (int i = 0; i < 8; i++) {
            float lo, hi;
            UNPACK2(lo, hi, A[i][c0]);
            const float x = (k & 1) ? hi : lo;
            PACK2(ak[i], x, x);
        }

        uint64_t pp[8];
        #pragma unroll
        for (int c = c0; c < 8; c++) {
            uint64_t s0, s1;
            MUL2(s0, ak[0], A[0][c]);
            MUL2(s1, ak[4], A[4][c]);
            FMA2(s0, ak[1], A[1][c], s0);
            FMA2(s1, ak[5], A[5][c], s1);
            FMA2(s0, ak[2], A[2][c], s0);
            FMA2(s1, ak[6], A[6][c], s1);
            FMA2(s0, ak[3], A[3][c], s0);
            FMA2(s1, ak[7], A[7][c], s1);
            ADD2(s0, s0, s1);
            const uint64_t o = shx1(s0);
            ADD2(pp[c], s0, o);
        }

        float plo, phi;
        UNPACK2(plo, phi, pp[c0]);
        const float pk = fmaxf((k & 1) ? phi : plo, 1e-30f);
        const float ninv = -frcp(pk);        // projection path
        const float r = rsqrtf(pk);          // normalization path (parallel)
        if (SCALEW) {
            float wl, wh;
            UNPACK2(wl, wh, w[c0]);
            if (k & 1) wh *= r; else wl *= r;
            PACK2(w[c0], wl, wh);
        } else if (writer) {
            rs_sm[k] = r;
        }
        uint64_t n2;
        PACK2(n2, ninv, ninv);

        #pragma unroll
        for (int c = cu; c < 8; c++) {
            uint64_t s;
            MUL2(s, pp[c], n2);
            if (!(k & 1) && c == cu) {       // pair contains j == k: mask lo half
                float sl, sh;
                UNPACK2(sl, sh, s);
                PACK2(s, 0.0f, sh);
            }
            #pragma unroll
            for (int i = 0; i < 8; i++) FMA2(A[i][c], s, ak[i], A[i][c]);
        }
    }
    // column 15 norm
    float n15 = 0.0f;
    #pragma unroll
    for (int i = 0; i < 8; i++) {
        float lo, hi;
        UNPACK2(lo, hi, A[i][7]);
        n15 = fmaf(hi, hi, n15);
    }
    n15 += __shfl_xor_sync(0xffffffffu, n15, 1);
    const float r = rsqrtf(fmaxf(n15, 1e-30f));
    if (SCALEW) {
        float wl, wh;
        UNPACK2(wl, wh, w[7]);
        wh *= r;
        PACK2(w[7], wl, wh);
    } else if (writer) {
        rs_sm[15] = r;
    }
}

__device__ __forceinline__ void load_mat(uint64_t (&A)[8][8], const float4* f4, int rbase) {
    #pragma unroll
    for (int i = 0; i < 8; i++) {
        const float4 q0 = __ldg(&f4[rbase + 4 * i + 0]);
        const float4 q1 = __ldg(&f4[rbase + 4 * i + 1]);
        const float4 q2 = __ldg(&f4[rbase + 4 * i + 2]);
        const float4 q3 = __ldg(&f4[rbase + 4 * i + 3]);
        PACK2(A[i][0], q0.x, q0.y); PACK2(A[i][1], q0.z, q0.w);
        PACK2(A[i][2], q1.x, q1.y); PACK2(A[i][3], q1.z, q1.w);
        PACK2(A[i][4], q2.x, q2.y); PACK2(A[i][5], q2.z, q2.w);
        PACK2(A[i][6], q3.x, q3.y); PACK2(A[i][7], q3.z, q3.w);
    }
}

__global__ void __launch_bounds__(64, 6)
inv1x1mm_svd_kernel(const float* __restrict__ data,
                    const float* __restrict__ paras,
                    float* __restrict__ out) {
    __shared__ float rs_sm[32][17];          // stride-17: conflict-free

    const int tid  = threadIdx.x;
    const int half = tid & 1;
    const int p    = tid >> 1;
    const int pos  = blockIdx.x * 32 + p;

    const float4* f4 = (const float4*)(paras + (size_t)pos * 528);

    uint64_t A[8][8];

    // ===== QR of U =====
    load_mat(A, f4, 4 + half * 32);
    mgs2<false>(A, nullptr, rs_sm[p], half == 0);

    // local partial dots v_j (uses U's Q before A is reloaded with V)
    const float4 d0 = __ldg((const float4*)(data + pos * 16 + half * 8));
    const float4 d1 = __ldg((const float4*)(data + pos * 16 + half * 8 + 4));
    uint64_t dd[8];
    PACK2(dd[0], d0.x, d0.x); PACK2(dd[1], d0.y, d0.y);
    PACK2(dd[2], d0.z, d0.z); PACK2(dd[3], d0.w, d0.w);
    PACK2(dd[4], d1.x, d1.x); PACK2(dd[5], d1.y, d1.y);
    PACK2(dd[6], d1.z, d1.z); PACK2(dd[7], d1.w, d1.w);

    uint64_t w[8];
    #pragma unroll
    for (int c = 0; c < 8; c++) {
        uint64_t s0, s1;
        MUL2(s0, dd[0], A[0][c]);
        MUL2(s1, dd[4], A[4][c]);
        FMA2(s0, dd[1], A[1][c], s0);
        FMA2(s1, dd[5], A[5][c], s1);
        FMA2(s0, dd[2], A[2][c], s0);
        FMA2(s1, dd[6], A[6][c], s1);
        FMA2(s0, dd[3], A[3][c], s0);
        FMA2(s1, dd[7], A[7][c], s1);
        ADD2(w[c], s0, s1);
    }

    // reload A with V now; the reduce/exp below hides the LDG latency
    load_mat(A, f4, 68 + half * 32);

    __syncwarp();   // partner's rs_sm writes -> my reads
    #pragma unroll
    for (int c = 0; c < 8; c++) {
        const uint64_t o = shx1(w[c]);
        ADD2(w[c], w[c], o);
        // ls pair for columns {2c, 2c+1}
        const float2 lsp = __ldg((const float2*)(paras + (size_t)pos * 528 + 2 * c));
        uint64_t m;
        PACK2(m, __expf(lsp.x) * rs_sm[p][2 * c],
                 __expf(lsp.y) * rs_sm[p][2 * c + 1]);
        MUL2(w[c], w[c], m);
    }

    // ===== QR of V ===== (folds 1/||b1_j|| into w)
    mgs2<true>(A, w, nullptr, false);

    // res_d = sum_j w_j * b1[d][j]  (d = my 8 local rows)
    float o[8];
    #pragma unroll
    for (int i = 0; i < 8; i++) {
        uint64_t s0, s1;
        MUL2(s0, w[0], A[i][0]);
        MUL2(s1, w[4], A[i][4]);
        FMA2(s0, w[1], A[i][1], s0);
        FMA2(s1, w[5], A[i][5], s1);
        FMA2(s0, w[2], A[i][2], s0);
        FMA2(s1, w[6], A[i][6], s1);
        FMA2(s0, w[3], A[i][3], s0);
        FMA2(s1, w[7], A[i][7], s1);
        ADD2(s0, s0, s1);
        float lo, hi;
        UNPACK2(lo, hi, s0);
        o[i] = lo + hi;
    }

    float4* o4 = (float4*)(out + pos * 16 + half * 8);
    o4[0] = make_float4(o[0], o[1], o[2], o[3]);
    o4[1] = make_float4(o[4], o[5], o[6], o[7]);
}

extern "C" void kernel_launch(void* const* d_in, const int* in_sizes, int n_in,
                              void* d_out, int out_size) {
    const float* data  = (const float*)d_in[0];
    const float* paras = (const float*)d_in[1];
    if (n_in >= 2 && in_sizes[0] > in_sizes[1]) {  // defensive ordering by size
        data  = (const float*)d_in[1];
        paras = (const float*)d_in[0];
    }
    inv1x1mm_svd_kernel<<<NPOS / 32, 64>>>(data, paras, (float*)d_out);
}